// round 15
// baseline (speedup 1.0000x reference)
#include <cuda_runtime.h>

// Problem constants (fixed by setup_inputs)
#define BB    64      // batch_size
#define NMAX  768     // max_num_nodes
#define FF    512     // hidden dim
#define HH    16      // num heads
#define NEG_INF_F (-1000000000.0f)

#define ATTN_BLOCKS_PER_B 144
#define ATTN_BLOCKS (BB * ATTN_BLOCKS_PER_B)          // 9216
#define DENSE_BLOCKS (BB * NMAX / 2)                   // 24576 (2 rows/block)
#define TOTAL_BLOCKS (ATTN_BLOCKS + DENSE_BLOCKS)      // 33792

__device__ int g_starts[BB + 1];

// Kernel 1: boundary detection, one thread per element. 128 blocks x 256
// threads = N exactly; every load front-batched, all SMs used ->
// launch + ~1 DRAM round trip (~4.4us measured).
__global__ void k_starts(const int* __restrict__ batch_ids, int N) {
    int i = blockIdx.x * blockDim.x + threadIdx.x;
    if (i >= N) return;
    int cur = batch_ids[i];
    int prev = (i == 0) ? -1 : batch_ids[i - 1];
    if (cur != prev) {
        for (int b = prev + 1; b <= cur; ++b) g_starts[b] = i;
    }
    if (i == N - 1) {
        for (int b = cur + 1; b <= BB; ++b) g_starts[b] = N;
    }
}

// Kernel 2 (fused): attn fill + dense gather, starts PRECOMPUTED (no per-block
// search -> no parked warps, unlike round-3's fused attempt).
// Blocks [0, ATTN_BLOCKS): attn[b,h,q,j] = (j < cnt[b]) ? 0 : -1e9.
//   Per-b stride 144*256 = 36864 = 192*192, multiple of the 192-float4 row ->
//   thread's column (and float4 value) loop-invariant: 64 pure STG.128.
// Blocks [ATTN_BLOCKS, TOTAL): dense gather + Dmask, 2 rows/block
//   (128 threads x float4 = 512 floats per row), sorted ids -> contiguous slice.
__global__ void k_work(const float* __restrict__ x,
                       float* __restrict__ dense,
                       float* __restrict__ dmask,
                       float4* __restrict__ attn) {
    const int blk = blockIdx.x;
    const int t = threadIdx.x;

    if (blk < ATTN_BLOCKS) {
        const int b = blk / ATTN_BLOCKS_PER_B;
        const int cnt = g_starts[b + 1] - g_starts[b];

        const long long per_b = (long long)HH * NMAX * (NMAX / 4); // 2,359,296
        const int idx0 = (blk - b * ATTN_BLOCKS_PER_B) * 256 + t;  // [0, 36864)
        const int j = (idx0 % (NMAX / 4)) * 4;                     // loop-invariant

        float4 v;
        v.x = (j + 0 < cnt) ? 0.0f : NEG_INF_F;
        v.y = (j + 1 < cnt) ? 0.0f : NEG_INF_F;
        v.z = (j + 2 < cnt) ? 0.0f : NEG_INF_F;
        v.w = (j + 3 < cnt) ? 0.0f : NEG_INF_F;

        float4* base = attn + (long long)b * per_b + idx0;
        const int stride = ATTN_BLOCKS_PER_B * 256; // 36864
        #pragma unroll 16
        for (int k = 0; k < 64; ++k) {
            base[(long long)k * stride] = v;
        }
    } else {
        const int dblk = blk - ATTN_BLOCKS;          // [0, 24576)
        const int b = dblk / (NMAX / 2);             // 384 blocks per graph
        const int start = g_starts[b];
        const int cnt = g_starts[b + 1] - start;

        const int row = dblk * 2 + (t >> 7);         // global dense row
        const int i = row - b * NMAX;                // within-graph index
        const bool valid = (i < cnt);
        const int c = t & 127;                       // float4 lane within row

        float4 v = make_float4(0.f, 0.f, 0.f, 0.f);
        if (valid) {
            v = reinterpret_cast<const float4*>(x + (size_t)(start + i) * FF)[c];
        }
        reinterpret_cast<float4*>(dense + (size_t)row * FF)[c] = v;

        if (c == 0) dmask[row] = valid ? 1.0f : 0.0f;
    }
}

extern "C" void kernel_launch(void* const* d_in, const int* in_sizes, int n_in,
                              void* d_out, int out_size) {
    const float* x         = (const float*)d_in[0];
    const int*   batch_ids = (const int*)d_in[1];
    int N = in_sizes[1]; // 32768

    float* out   = (float*)d_out;
    float* dense = out;                                  // B*NMAX*F
    float* dmask = dense + (size_t)BB * NMAX * FF;       // B*NMAX
    float* attn  = dmask + (size_t)BB * NMAX;            // B*H*NMAX*NMAX

    k_starts<<<(N + 255) / 256, 256>>>(batch_ids, N);
    k_work<<<TOTAL_BLOCKS, 256>>>(x, dense, dmask, (float4*)attn);
}